// round 5
// baseline (speedup 1.0000x reference)
#include <cuda_runtime.h>
#include <cuda_bf16.h>
#include <cstdint>

// FlowBasedDensityPotential: energy = 0.5 * sum(|grad phi|^2), central diffs
// (one-sided at boundaries) on a 2048x2048 f32 grid. 'pos' input is dead.
//
// R4 = R3 with the missing <cstdint> include fixed (compile error only).
// cp.async (LDGSTS) tile into shared memory: R1/R2 showed ptxas pins the
// kernel at 32 regs and serializes register-destined loads (MLP ~2, issue
// 35%, DRAM 21%). LDGSTS bypasses the register file: all of a block's loads
// issue up-front with zero dependencies, then compute runs out of smem with
// a rolling 3-row register window.

#define NX 2048
#define NY 2048

#define TR 16                    // computed rows per tile
#define TC 512                   // computed cols per tile
#define PITCH 520                // smem row pitch in floats (TC + 8 halo)
#define SROWS 18                 // TR + 2 halo rows
#define BLOCK 256
#define GX (NY / TC)             // 4 tiles across
#define GY (NX / TR)             // 128 tiles down
#define NUM_BLOCKS (GX * GY)     // 512
#define CHUNKS (SROWS * (PITCH / 4))   // 18 * 130 = 2340 16B chunks

__device__ double       g_partials[NUM_BLOCKS];
__device__ unsigned int g_ticket = 0;

__device__ __forceinline__ void cp_async16(unsigned int smem_addr, const void* gptr)
{
    asm volatile("cp.async.cg.shared.global [%0], [%1], 16;\n"
                 :: "r"(smem_addr), "l"(gptr));
}

__global__ void __launch_bounds__(BLOCK)
flow_energy_kernel(const float* __restrict__ phi, float* __restrict__ out)
{
    __shared__ float s[SROWS * PITCH];   // 37440 B

    const int tid = threadIdx.x;
    const int tx  = blockIdx.x & (GX - 1);     // tile col
    const int ty  = blockIdx.x >> 2;           // tile row
    const int r0  = ty * TR;                   // first computed global row
    const int c0  = tx * TC;                   // first computed global col

    // ---- LOAD PHASE: stream tile + halo into smem via cp.async ----
    // smem row lr covers global row (r0 - 1 + lr), clamped.
    // smem float4-col lc covers global cols (c0 - 4 + 4*lc .. +3), clamped.
    // Clamped entries are never read (one-sided boundary formulas skip them).
    {
        const unsigned int sbase = (unsigned int)__cvta_generic_to_shared(s);
        #pragma unroll 5
        for (int idx = tid; idx < CHUNKS; idx += BLOCK) {
            const int lr = idx / (PITCH / 4);
            const int lc = idx - lr * (PITCH / 4);
            int gr = r0 - 1 + lr;
            gr = gr < 0 ? 0 : (gr > NX - 1 ? NX - 1 : gr);
            int gc = c0 - 4 + lc * 4;
            gc = gc < 0 ? 0 : (gc > NY - 4 ? NY - 4 : gc);
            cp_async16(sbase + (unsigned int)(idx * 16),
                       phi + (size_t)gr * NY + gc);
        }
        asm volatile("cp.async.commit_group;\n");
        asm volatile("cp.async.wait_group 0;\n" ::: "memory");
    }
    __syncthreads();

    // ---- COMPUTE PHASE ----
    // cg = tid & 127 -> float4 col group (covers TC=512 cols),
    // rr = tid >> 7 -> which half of the 16 rows; each thread walks 8
    // consecutive rows with a rolling up/cur/down window.
    const float C1 = 1024.0f;   // 1/(2h)
    const float C2 = 2048.0f;   // 1/h

    const int cg = tid & 127;
    const int rr = tid >> 7;
    const int sc = 4 + cg * 4;            // smem float index of this group's col 0
    const int j0 = c0 + cg * 4;           // global col of element 0
    const int sr0 = 1 + rr * 8;           // first computed smem row for this thread

    float acc = 0.0f;

    const float* srow = s + sr0 * PITCH + sc;
    float4 up  = *reinterpret_cast<const float4*>(srow - PITCH);
    float4 cur = *reinterpret_cast<const float4*>(srow);

    #pragma unroll
    for (int k = 0; k < 8; ++k) {
        const int i = r0 + rr * 8 + k;    // global row
        const float* rowp = srow + k * PITCH;
        const float4 down = *reinterpret_cast<const float4*>(rowp + PITCH);

        float4 dx;
        if (i == 0) {
            dx.x = (down.x - cur.x) * C2;
            dx.y = (down.y - cur.y) * C2;
            dx.z = (down.z - cur.z) * C2;
            dx.w = (down.w - cur.w) * C2;
        } else if (i == NX - 1) {
            dx.x = (cur.x - up.x) * C2;
            dx.y = (cur.y - up.y) * C2;
            dx.z = (cur.z - up.z) * C2;
            dx.w = (cur.w - up.w) * C2;
        } else {
            dx.x = (down.x - up.x) * C1;
            dx.y = (down.y - up.y) * C1;
            dx.z = (down.z - up.z) * C1;
            dx.w = (down.w - up.w) * C1;
        }

        const float left  = rowp[-1];
        const float right = rowp[4];

        const float dy0 = (j0 == 0)      ? (cur.y - cur.x) * C2 : (cur.y - left) * C1;
        const float dy1 = (cur.z - cur.x) * C1;
        const float dy2 = (cur.w - cur.y) * C1;
        const float dy3 = (j0 + 4 == NY) ? (cur.w - cur.z) * C2 : (right - cur.z) * C1;

        acc += dx.x * dx.x + dy0 * dy0;
        acc += dx.y * dx.y + dy1 * dy1;
        acc += dx.z * dx.z + dy2 * dy2;
        acc += dx.w * dx.w + dy3 * dy3;

        up  = cur;
        cur = down;
    }

    // ---- block reduction (float tree; 32 terms/thread) ----
    #pragma unroll
    for (int off = 16; off; off >>= 1)
        acc += __shfl_xor_sync(0xffffffffu, acc, off);

    __shared__ float  s_warp[BLOCK / 32];
    __shared__ bool   s_is_last;
    if ((tid & 31) == 0)
        s_warp[tid >> 5] = acc;
    __syncthreads();

    if (tid < 32) {
        float v = (tid < BLOCK / 32) ? s_warp[tid] : 0.0f;
        #pragma unroll
        for (int off = 4; off; off >>= 1)
            v += __shfl_xor_sync(0xffffffffu, v, off);
        if (tid == 0) {
            g_partials[blockIdx.x] = (double)v;
            __threadfence();
            unsigned int tk = atomicAdd(&g_ticket, 1u);
            s_is_last = (tk == (unsigned int)(gridDim.x - 1));
        }
    }
    __syncthreads();

    // ---- last block: sum the 512 double partials, write scalar, reset ----
    if (s_is_last) {
        double d = 0.0;
        for (int k = tid; k < NUM_BLOCKS; k += BLOCK)
            d += g_partials[k];
        #pragma unroll
        for (int off = 16; off; off >>= 1)
            d += __shfl_xor_sync(0xffffffffu, d, off);

        __shared__ double s_dwarp[BLOCK / 32];
        if ((tid & 31) == 0)
            s_dwarp[tid >> 5] = d;
        __syncthreads();
        if (tid < 32) {
            double v = (tid < BLOCK / 32) ? s_dwarp[tid] : 0.0;
            #pragma unroll
            for (int off = 4; off; off >>= 1)
                v += __shfl_xor_sync(0xffffffffu, v, off);
            if (tid == 0) {
                out[0] = (float)(0.5 * v);
                g_ticket = 0;   // reset for next (graph-replayed) launch
            }
        }
    }
}

extern "C" void kernel_launch(void* const* d_in, const int* in_sizes, int n_in,
                              void* d_out, int out_size)
{
    // Select phi by element count (2048*2048); 'pos' (2,000,000 elems) unused.
    const float* phi = nullptr;
    for (int i = 0; i < n_in; ++i) {
        if (in_sizes[i] == NX * NY) { phi = (const float*)d_in[i]; break; }
    }
    if (!phi) phi = (const float*)d_in[n_in - 1];

    flow_energy_kernel<<<NUM_BLOCKS, BLOCK>>>(phi, (float*)d_out);
}